// round 1
// baseline (speedup 1.0000x reference)
#include <cuda_runtime.h>
#include <math.h>

#define NROWS 32768          // B*S = 128*256
#define INV_SQRT_HD 0.17677669529663687f   // 1/sqrt(32)

// Scratch (allocation-free rule: __device__ globals)
__device__ float g_weff[128 * 512];   // fused weights, [j][col], col: 0-127 q, 128-255 k, 256-383 v, 384-511 wo
__device__ float g_q[NROWS * 128];    // [b][h][s][d]
__device__ float g_k[NROWS * 128];
__device__ float g_v[NROWS * 128];
__device__ float g_o[NROWS * 128];    // [b][s][h*32+d]

// ---------------------------------------------------------------------------
// Kernel 1: fold LoRA into effective weights, store transposed for GEMM.
// weff[j][g*128+i] = w_g[i][j] + 2.0 * sum_r B_g[i][r] * A_g[r][j]   (g<3)
// weff[j][384+i]   = wo[i][j]
// ---------------------------------------------------------------------------
__global__ void fuse_weights(const float* __restrict__ wq, const float* __restrict__ wk,
                             const float* __restrict__ wv, const float* __restrict__ wo,
                             const float* __restrict__ Aq, const float* __restrict__ Bq,
                             const float* __restrict__ Ak, const float* __restrict__ Bk,
                             const float* __restrict__ Av, const float* __restrict__ Bv) {
    int col = blockIdx.x;           // 0..511
    int j = threadIdx.x;            // 0..127
    int g = col >> 7;
    int i = col & 127;
    const float* w = (g == 0) ? wq : (g == 1) ? wk : (g == 2) ? wv : wo;
    float acc = w[i * 128 + j];
    if (g < 3) {
        const float* A  = (g == 0) ? Aq : (g == 1) ? Ak : Av;
        const float* Bm = (g == 0) ? Bq : (g == 1) ? Bk : Bv;
        float s = 0.f;
#pragma unroll
        for (int r = 0; r < 8; r++) s += Bm[i * 8 + r] * A[r * 128 + j];
        acc += 2.0f * s;            // SCALING = 16/8
    }
    g_weff[j * 512 + col] = acc;
}

// ---------------------------------------------------------------------------
// Kernel 2: QKV GEMM (32768 x 384, K=128) + fused RoPE epilogue, scatter to
// [b][h][s][d] layout. BM=64 BN=64 BK=32, 16x16 threads, 4x4 per thread.
// ---------------------------------------------------------------------------
__global__ __launch_bounds__(256) void qkv_gemm(const float* __restrict__ X) {
    __shared__ float As[64][33];
    __shared__ float Bs[32][68];
    int tx = threadIdx.x, ty = threadIdx.y;
    int tid = ty * 16 + tx;
    int m0 = blockIdx.x * 64;
    int n0 = blockIdx.y * 64;

    float acc[4][4] = {};

    for (int kt = 0; kt < 4; kt++) {
#pragma unroll
        for (int t = 0; t < 8; t++) {
            int e = tid + t * 256;          // 64*32 = 2048 elements
            int r = e >> 5, kk = e & 31;
            As[r][kk] = X[(m0 + r) * 128 + kt * 32 + kk];
        }
#pragma unroll
        for (int t = 0; t < 8; t++) {
            int e = tid + t * 256;          // 32*64 = 2048 elements
            int kr = e >> 6, c = e & 63;
            Bs[kr][c] = g_weff[(kt * 32 + kr) * 512 + n0 + c];
        }
        __syncthreads();
#pragma unroll
        for (int kk = 0; kk < 32; kk++) {
            float a[4];
#pragma unroll
            for (int i = 0; i < 4; i++) a[i] = As[ty * 4 + i][kk];
            float4 bv = *(const float4*)&Bs[kk][tx * 4];
            float bb[4] = {bv.x, bv.y, bv.z, bv.w};
#pragma unroll
            for (int i = 0; i < 4; i++)
#pragma unroll
                for (int jj = 0; jj < 4; jj++) acc[i][jj] += a[i] * bb[jj];
        }
        __syncthreads();
    }

    // Epilogue: RoPE (groups 0,1) + scatter to [b][h][s][d]
    int g = n0 >> 7;                         // 0=q, 1=k, 2=v
    float* dst = (g == 0) ? g_q : (g == 1) ? g_k : g_v;
#pragma unroll
    for (int i = 0; i < 4; i++) {
        int row = m0 + ty * 4 + i;
        int b = row >> 8, s = row & 255;
#pragma unroll
        for (int jp = 0; jp < 2; jp++) {
            int cl = (n0 & 127) + tx * 4 + jp * 2;   // col within 0..127
            int h = cl >> 5, d = cl & 31;
            float x1 = acc[i][jp * 2], x2 = acc[i][jp * 2 + 1];
            if (g < 2) {
                int p = d >> 1;                       // pair index 0..15
                float invf = __powf(10000.0f, -(float)p * (1.0f / 16.0f));
                float ang = (float)s * invf;
                float sn, cs;
                sincosf(ang, &sn, &cs);
                float y1 = x1 * cs - x2 * sn;
                float y2 = x1 * sn + x2 * cs;
                x1 = y1; x2 = y2;
            }
            int base = ((b * 4 + h) * 256 + s) * 32 + d;
            dst[base]     = x1;
            dst[base + 1] = x2;
        }
    }
}

// ---------------------------------------------------------------------------
// Kernel 3: causal attention per (b,h). K,V resident in smem (pad 33).
// 8 warps; each warp processes query-row pairs (s, s+8) to halve smem traffic.
// ---------------------------------------------------------------------------
__global__ __launch_bounds__(256) void attn_kernel() {
    extern __shared__ float sm[];
    float* Ksm = sm;                    // 256*33
    float* Vsm = sm + 256 * 33;         // 256*33
    float* Psm = sm + 2 * 256 * 33;     // 8 warps * 2 rows * 256

    int bh = blockIdx.x;
    const float* Qb = g_q + bh * 8192;
    const float* Kb = g_k + bh * 8192;
    const float* Vb = g_v + bh * 8192;
    int tid = threadIdx.x;

    for (int e = tid; e < 8192; e += 256) {
        int s = e >> 5, d = e & 31;
        Ksm[s * 33 + d] = Kb[e];
        Vsm[s * 33 + d] = Vb[e];
    }
    __syncthreads();

    int w = tid >> 5, lane = tid & 31;
    float* Pa = Psm + w * 512;
    float* Pb = Pa + 256;
    int b = bh >> 2, h = bh & 3;

    for (int t = 0; t < 16; t++) {
        int sa = w + 16 * t;            // {w, w+16, ...}
        int sb = sa + 8;

        float qa[32], qb[32];
#pragma unroll
        for (int d = 0; d < 32; d++) {
            qa[d] = Qb[sa * 32 + d];
            qb[d] = Qb[sb * 32 + d];
        }
        int nja = sa >> 5, njb = sb >> 5;
        float sca[8], scb[8];
#pragma unroll
        for (int j = 0; j < 8; j++) { sca[j] = -INFINITY; scb[j] = -INFINITY; }

        for (int j = 0; j <= njb; j++) {
            int kk = j * 32 + lane;
            const float* Kr = &Ksm[kk * 33];
            float da = 0.f, db = 0.f;
#pragma unroll
            for (int d = 0; d < 32; d++) {
                float kv = Kr[d];
                da += qa[d] * kv;
                db += qb[d] * kv;
            }
            if (j <= nja && kk <= sa) sca[j] = da * INV_SQRT_HD;
            if (kk <= sb)             scb[j] = db * INV_SQRT_HD;
        }

        // softmax (two rows)
        float ma = -INFINITY, mb = -INFINITY;
#pragma unroll
        for (int j = 0; j < 8; j++) { ma = fmaxf(ma, sca[j]); mb = fmaxf(mb, scb[j]); }
#pragma unroll
        for (int o = 16; o > 0; o >>= 1) {
            ma = fmaxf(ma, __shfl_xor_sync(0xffffffffu, ma, o));
            mb = fmaxf(mb, __shfl_xor_sync(0xffffffffu, mb, o));
        }
        float suma = 0.f, sumb = 0.f;
        float ea[8], eb[8];
#pragma unroll
        for (int j = 0; j < 8; j++) {
            ea[j] = expf(sca[j] - ma);
            eb[j] = expf(scb[j] - mb);
            suma += ea[j]; sumb += eb[j];
        }
#pragma unroll
        for (int o = 16; o > 0; o >>= 1) {
            suma += __shfl_xor_sync(0xffffffffu, suma, o);
            sumb += __shfl_xor_sync(0xffffffffu, sumb, o);
        }
        float ia = 1.f / suma, ib = 1.f / sumb;
#pragma unroll
        for (int j = 0; j < 8; j++) {
            Pa[j * 32 + lane] = ea[j] * ia;
            Pb[j * 32 + lane] = eb[j] * ib;
        }
        __syncwarp();

        // PV: lane = output dim d
        float aca = 0.f, acb = 0.f;
        int ka_end = sa + 1, kb_end = sb + 1;
#pragma unroll 4
        for (int k = 0; k < ka_end; k++) {
            float vv = Vsm[k * 33 + lane];
            aca += Pa[k] * vv;
            acb += Pb[k] * vv;
        }
#pragma unroll 4
        for (int k = ka_end; k < kb_end; k++) {
            acb += Pb[k] * Vsm[k * 33 + lane];
        }
        g_o[((b << 8) + sa) * 128 + h * 32 + lane] = aca;
        g_o[((b << 8) + sb) * 128 + h * 32 + lane] = acb;
        __syncwarp();
    }
}

// ---------------------------------------------------------------------------
// Kernel 4: output projection 32768x128 @ woT (weff cols 384..511) -> d_out
// ---------------------------------------------------------------------------
__global__ __launch_bounds__(256) void out_gemm(float* __restrict__ out) {
    __shared__ float As[64][33];
    __shared__ float Bs[32][68];
    int tx = threadIdx.x, ty = threadIdx.y;
    int tid = ty * 16 + tx;
    int m0 = blockIdx.x * 64;
    int n0 = blockIdx.y * 64;

    float acc[4][4] = {};

    for (int kt = 0; kt < 4; kt++) {
#pragma unroll
        for (int t = 0; t < 8; t++) {
            int e = tid + t * 256;
            int r = e >> 5, kk = e & 31;
            As[r][kk] = g_o[(m0 + r) * 128 + kt * 32 + kk];
        }
#pragma unroll
        for (int t = 0; t < 8; t++) {
            int e = tid + t * 256;
            int kr = e >> 6, c = e & 63;
            Bs[kr][c] = g_weff[(kt * 32 + kr) * 512 + 384 + n0 + c];
        }
        __syncthreads();
#pragma unroll
        for (int kk = 0; kk < 32; kk++) {
            float a[4];
#pragma unroll
            for (int i = 0; i < 4; i++) a[i] = As[ty * 4 + i][kk];
            float4 bv = *(const float4*)&Bs[kk][tx * 4];
            float bb[4] = {bv.x, bv.y, bv.z, bv.w};
#pragma unroll
            for (int i = 0; i < 4; i++)
#pragma unroll
                for (int jj = 0; jj < 4; jj++) acc[i][jj] += a[i] * bb[jj];
        }
        __syncthreads();
    }

#pragma unroll
    for (int i = 0; i < 4; i++) {
        int row = m0 + ty * 4 + i;
        float4 v = make_float4(acc[i][0], acc[i][1], acc[i][2], acc[i][3]);
        *(float4*)&out[row * 128 + n0 + tx * 4] = v;
    }
}

// ---------------------------------------------------------------------------
extern "C" void kernel_launch(void* const* d_in, const int* in_sizes, int n_in,
                              void* d_out, int out_size) {
    const float* x  = (const float*)d_in[0];
    const float* wq = (const float*)d_in[1];
    const float* wk = (const float*)d_in[2];
    const float* wv = (const float*)d_in[3];
    const float* wo = (const float*)d_in[4];
    const float* Aq = (const float*)d_in[5];
    const float* Bq = (const float*)d_in[6];
    const float* Ak = (const float*)d_in[7];
    const float* Bk = (const float*)d_in[8];
    const float* Av = (const float*)d_in[9];
    const float* Bv = (const float*)d_in[10];
    float* out = (float*)d_out;

    fuse_weights<<<512, 128>>>(wq, wk, wv, wo, Aq, Bq, Ak, Bk, Av, Bv);
    qkv_gemm<<<dim3(512, 6), dim3(16, 16)>>>(x);

    int smem_bytes = (2 * 256 * 33 + 8 * 512) * (int)sizeof(float);   // 83968
    cudaFuncSetAttribute(attn_kernel, cudaFuncAttributeMaxDynamicSharedMemorySize, smem_bytes);
    attn_kernel<<<512, 256, smem_bytes>>>();

    out_gemm<<<dim3(512, 2), dim3(16, 16)>>>(out);
}